// round 8
// baseline (speedup 1.0000x reference)
#include <cuda_runtime.h>
#include <math.h>

#define BB 64
#define NN 8192
#define WW 64
#define HH 4
#define CTRL 792   // H*(3W+6)

// ---------------- scratch (no allocation allowed) ----------------
__device__ float g_keys [BB*HH*WW];   // tanh(keys)
__device__ float g_erase[BB*HH*WW];   // sigmoid(erase)
__device__ float g_wvec [BB*HH*WW];   // tanh(write)
__device__ float g_params[BB*HH*8];   // beta,gate,s0,s1,s2,gamma,keynorm
__device__ float g_scores[(size_t)BB*HH*NN];  // beta * cosine
__device__ float g_w     [(size_t)BB*HH*NN];  // final write distribution

__device__ __forceinline__ float softplusf(float x){
    return x > 20.f ? x : log1pf(expf(x));
}
__device__ __forceinline__ float sigmoidf(float x){
    return 1.f/(1.f + expf(-x));
}

// ---------------- k0: control transforms (tiny) ----------------
__global__ void k0_controls(const float* __restrict__ ctrl){
    int bh = blockIdx.x;                 // b*4+h
    int b  = bh >> 2, h = bh & 3;
    int t  = threadIdx.x;                // 64 threads
    const float* c = ctrl + b*CTRL;

    float k = tanhf(c[h*WW + t]);
    g_keys [bh*WW + t] = k;
    g_erase[bh*WW + t] = sigmoidf(c[256 + h*WW + t]);
    g_wvec [bh*WW + t] = tanhf(c[512 + h*WW + t]);

    __shared__ float s2[2];
    float sq = k*k;
    #pragma unroll
    for (int o = 16; o; o >>= 1) sq += __shfl_xor_sync(0xffffffffu, sq, o);
    if ((t & 31) == 0) s2[t >> 5] = sq;
    __syncthreads();
    if (t == 0){
        float nrm   = sqrtf(s2[0] + s2[1]);
        float beta  = softplusf(c[768 + h]);
        float gate  = sigmoidf(c[772 + h]);
        float gamma = 1.f + softplusf(c[788 + h]);
        float a0 = c[776 + h*3 + 0], a1 = c[776 + h*3 + 1], a2 = c[776 + h*3 + 2];
        float m  = fmaxf(a0, fmaxf(a1, a2));
        float e0 = expf(a0 - m), e1 = expf(a1 - m), e2 = expf(a2 - m);
        float inv = 1.f/(e0 + e1 + e2);
        float* p = g_params + bh*8;
        p[0]=beta; p[1]=gate; p[2]=e0*inv; p[3]=e1*inv; p[4]=e2*inv; p[5]=gamma; p[6]=nrm;
    }
}

// ---------------- k1: beta * cosine scores, SMEM-staged coalesced loads --------
// Phase A: 256 threads load 64 rows (1024 float4) fully coalesced into padded SMEM.
// Phase B: 4 lanes per row compute dots from SMEM, 2 shuffle rounds.
#define K1_ROWSPB 64
#define TP 17                     // row pitch in float4 (padding breaks conflicts)
__global__ __launch_bounds__(256) void k1_scores(const float* __restrict__ mem){
    int b  = blockIdx.y;
    int n0 = blockIdx.x * K1_ROWSPB;
    __shared__ float4 tile[K1_ROWSPB * TP];
    __shared__ float skey[HH*WW];
    __shared__ float sb[HH], skn[HH];
    int t = threadIdx.x;
    skey[t] = g_keys[b*HH*WW + t];
    if (t < HH){ sb[t] = g_params[(b*HH + t)*8 + 0]; skn[t] = g_params[(b*HH + t)*8 + 6]; }

    // coalesced load: warp covers 32 consecutive float4 (512B, 4 lines)
    const float4* gsrc = (const float4*)(mem + (size_t)b*NN*WW) + (size_t)blockIdx.x*(K1_ROWSPB*16);
    float4 ld[4];
    #pragma unroll
    for (int i = 0; i < 4; i++) ld[i] = __ldcs(gsrc + t + 256*i);
    #pragma unroll
    for (int i = 0; i < 4; i++){
        int g = t + 256*i;
        tile[(g >> 4)*TP + (g & 15)] = ld[i];
    }
    __syncthreads();

    int seg = t & 3;            // which 16-float segment of W
    int rloc = t >> 2;          // local row 0..63
    const float4* mr = tile + rloc*TP + seg*4;
    float4 m0 = mr[0], m1 = mr[1], m2 = mr[2], m3 = mr[3];

    float sq = m0.x*m0.x + m0.y*m0.y + m0.z*m0.z + m0.w*m0.w
             + m1.x*m1.x + m1.y*m1.y + m1.z*m1.z + m1.w*m1.w
             + m2.x*m2.x + m2.y*m2.y + m2.z*m2.z + m2.w*m2.w
             + m3.x*m3.x + m3.y*m3.y + m3.z*m3.z + m3.w*m3.w;

    float d[HH];
    #pragma unroll
    for (int h = 0; h < HH; h++){
        const float4* kp = (const float4*)(skey + h*WW) + seg*4;
        float4 k0 = kp[0], k1 = kp[1], k2 = kp[2], k3 = kp[3];
        d[h] = m0.x*k0.x + m0.y*k0.y + m0.z*k0.z + m0.w*k0.w
             + m1.x*k1.x + m1.y*k1.y + m1.z*k1.z + m1.w*k1.w
             + m2.x*k2.x + m2.y*k2.y + m2.z*k2.z + m2.w*k2.w
             + m3.x*k3.x + m3.y*k3.y + m3.z*k3.z + m3.w*k3.w;
    }

    #pragma unroll
    for (int o = 1; o <= 2; o <<= 1){
        sq   += __shfl_xor_sync(0xffffffffu, sq,   o);
        d[0] += __shfl_xor_sync(0xffffffffu, d[0], o);
        d[1] += __shfl_xor_sync(0xffffffffu, d[1], o);
        d[2] += __shfl_xor_sync(0xffffffffu, d[2], o);
        d[3] += __shfl_xor_sync(0xffffffffu, d[3], o);
    }

    if (seg == 0){
        float mn = sqrtf(sq);
        size_t base = (size_t)b*HH*NN + n0 + rloc;
        #pragma unroll
        for (int h = 0; h < HH; h++)
            g_scores[base + (size_t)h*NN] = sb[h]*d[h]/(skn[h]*mn + 1e-8f);
    }
}

// ---------------- k2: softmax + interp + shift + sharpen ----------------
#define K2T 1024
#define VT  8
__device__ __forceinline__ float blk_reduce(float v, bool is_max, float* red, float* bc){
    int t = threadIdx.x, lane = t & 31, wid = t >> 5;
    #pragma unroll
    for (int o = 16; o; o >>= 1){
        float u = __shfl_xor_sync(0xffffffffu, v, o);
        v = is_max ? fmaxf(v, u) : (v + u);
    }
    __syncthreads();                 // protect red/bc from previous round
    if (lane == 0) red[wid] = v;
    __syncthreads();
    if (t == 0){
        float a = red[0];
        #pragma unroll
        for (int k = 1; k < K2T/32; k++) a = is_max ? fmaxf(a, red[k]) : (a + red[k]);
        *bc = a;
    }
    __syncthreads();
    return *bc;
}

__global__ __launch_bounds__(K2T) void k2_weights(const float* __restrict__ prev){
    int bh = blockIdx.x;
    __shared__ float sm[NN];
    __shared__ float red[K2T/32];
    __shared__ float bc;
    int t = threadIdx.x;

    const float* p = g_params + bh*8;
    float gate = p[1], s0 = p[2], s1 = p[3], s2 = p[4], gamma = p[5];

    const float* sc = g_scores + (size_t)bh*NN;
    const float* pr = prev     + (size_t)bh*NN;

    float4 v0 = __ldcs((const float4*)sc + t*2);
    float4 v1 = __ldcs((const float4*)sc + t*2 + 1);
    float4 p0 = ((const float4*)pr)[t*2];
    float4 p1 = ((const float4*)pr)[t*2 + 1];

    float v[VT] = {v0.x, v0.y, v0.z, v0.w, v1.x, v1.y, v1.z, v1.w};
    float pv[VT] = {p0.x, p0.y, p0.z, p0.w, p1.x, p1.y, p1.z, p1.w};

    float lmax = v[0];
    #pragma unroll
    for (int j = 1; j < VT; j++) lmax = fmaxf(lmax, v[j]);
    float M = blk_reduce(lmax, true, red, &bc);

    float lsum = 0.f;
    #pragma unroll
    for (int j = 0; j < VT; j++){ v[j] = __expf(v[j] - M); lsum += v[j]; }
    float S = blk_reduce(lsum, false, red, &bc);
    float invS = 1.f / S;

    #pragma unroll
    for (int j = 0; j < VT; j++)
        sm[t*VT + j] = gate * (v[j] * invS) + (1.f - gate) * pv[j];
    __syncthreads();

    float ls = 0.f;
    #pragma unroll
    for (int j = 0; j < VT; j++){
        int n  = t*VT + j;
        int nm = (n + NN - 1) & (NN - 1);
        int np = (n + 1) & (NN - 1);
        float x = s0*sm[nm] + s1*sm[n] + s2*sm[np];
        float pw = __powf(x, gamma);
        v[j] = pw;
        ls += pw;
    }
    float T = blk_reduce(ls, false, red, &bc);
    float invT = 1.f / (T + 1e-8f);

    float* wout = g_w + (size_t)bh*NN;
    float4 o0 = {v[0]*invT, v[1]*invT, v[2]*invT, v[3]*invT};
    float4 o1 = {v[4]*invT, v[5]*invT, v[6]*invT, v[7]*invT};
    ((float4*)wout)[t*2]     = o0;
    ((float4*)wout)[t*2 + 1] = o1;
}

// ---------------- k3: erase/add update, MLP=8 front-batched ----------------
#define K3_ROWS 128
__global__ __launch_bounds__(256) void k3_out(const float* __restrict__ mem,
                                              float* __restrict__ out){
    int b  = blockIdx.y;
    int n0 = blockIdx.x * K3_ROWS;
    __shared__ float se[HH][WW], sv[HH][WW];
    __shared__ float sa[HH][K3_ROWS];
    int t = threadIdx.x;
    se[t >> 6][t & 63] = g_erase[b*HH*WW + t];
    sv[t >> 6][t & 63] = g_wvec [b*HH*WW + t];
    {   // coalesced preload of the 4x128 weight tile (2 per thread)
        int i0 = t, i1 = t + 256;
        sa[i0 >> 7][i0 & 127] = g_w[((size_t)b*HH + (i0 >> 7))*NN + n0 + (i0 & 127)];
        sa[i1 >> 7][i1 & 127] = g_w[((size_t)b*HH + (i1 >> 7))*NN + n0 + (i1 & 127)];
    }
    __syncthreads();

    int lane = t & 15, r = t >> 4;
    float4 e0 = ((const float4*)se[0])[lane];
    float4 e1 = ((const float4*)se[1])[lane];
    float4 e2 = ((const float4*)se[2])[lane];
    float4 e3 = ((const float4*)se[3])[lane];
    float4 w0 = ((const float4*)sv[0])[lane];
    float4 w1 = ((const float4*)sv[1])[lane];
    float4 w2 = ((const float4*)sv[2])[lane];
    float4 w3 = ((const float4*)sv[3])[lane];

    size_t base = ((size_t)b*NN + n0 + r)*16 + lane;

    float4 m[8];
    #pragma unroll
    for (int i = 0; i < 8; i++)
        m[i] = __ldcs((const float4*)mem + base + (size_t)16*16*i);

    #pragma unroll
    for (int i = 0; i < 8; i++){
        int rr = r + 16*i;
        float a0 = sa[0][rr], a1 = sa[1][rr], a2 = sa[2][rr], a3 = sa[3][rr];
        float4 o;
        o.x = m[i].x*(1.f-a0*e0.x)*(1.f-a1*e1.x)*(1.f-a2*e2.x)*(1.f-a3*e3.x)
            + a0*w0.x + a1*w1.x + a2*w2.x + a3*w3.x;
        o.y = m[i].y*(1.f-a0*e0.y)*(1.f-a1*e1.y)*(1.f-a2*e2.y)*(1.f-a3*e3.y)
            + a0*w0.y + a1*w1.y + a2*w2.y + a3*w3.y;
        o.z = m[i].z*(1.f-a0*e0.z)*(1.f-a1*e1.z)*(1.f-a2*e2.z)*(1.f-a3*e3.z)
            + a0*w0.z + a1*w1.z + a2*w2.z + a3*w3.z;
        o.w = m[i].w*(1.f-a0*e0.w)*(1.f-a1*e1.w)*(1.f-a2*e2.w)*(1.f-a3*e3.w)
            + a0*w0.w + a1*w1.w + a2*w2.w + a3*w3.w;
        __stcs((float4*)out + base + (size_t)16*16*i, o);
    }
}

// ---------------- launch ----------------
extern "C" void kernel_launch(void* const* d_in, const int* in_sizes, int n_in,
                              void* d_out, int out_size) {
    const float* mem  = (const float*)d_in[0];   // [B,N,W]
    const float* ctrl = (const float*)d_in[1];   // [B,792]
    const float* prev = (const float*)d_in[2];   // [B,H,N]
    float* out = (float*)d_out;                  // [B,N,W]

    k0_controls<<<BB*HH, 64>>>(ctrl);
    k1_scores  <<<dim3(NN/K1_ROWSPB, BB), 256>>>(mem);
    k2_weights <<<BB*HH, K2T>>>(prev);
    k3_out     <<<dim3(NN/K3_ROWS, BB), 256>>>(mem, out);
    (void)in_sizes; (void)n_in; (void)out_size;
}

// round 9
// speedup vs baseline: 1.2673x; 1.2673x over previous
#include <cuda_runtime.h>
#include <math.h>

#define BB 64
#define NN 8192
#define WW 64
#define HH 4
#define CTRL 792   // H*(3W+6)

// ---------------- scratch (no allocation allowed) ----------------
__device__ float g_keys [BB*HH*WW];   // tanh(keys)
__device__ float g_erase[BB*HH*WW];   // sigmoid(erase)
__device__ float g_wvec [BB*HH*WW];   // tanh(write)
__device__ float g_params[BB*HH*8];   // beta,gate,s0,s1,s2,gamma,keynorm
__device__ float g_scores[(size_t)BB*HH*NN];  // beta * cosine
__device__ float g_w     [(size_t)BB*HH*NN];  // final write distribution

__device__ __forceinline__ float softplusf(float x){
    return x > 20.f ? x : log1pf(expf(x));
}
__device__ __forceinline__ float sigmoidf(float x){
    return 1.f/(1.f + expf(-x));
}

// ---------------- k0: control transforms (tiny) ----------------
__global__ void k0_controls(const float* __restrict__ ctrl){
    int bh = blockIdx.x;                 // b*4+h
    int b  = bh >> 2, h = bh & 3;
    int t  = threadIdx.x;                // 64 threads
    const float* c = ctrl + b*CTRL;

    float k = tanhf(c[h*WW + t]);
    g_keys [bh*WW + t] = k;
    g_erase[bh*WW + t] = sigmoidf(c[256 + h*WW + t]);
    g_wvec [bh*WW + t] = tanhf(c[512 + h*WW + t]);

    __shared__ float s2[2];
    float sq = k*k;
    #pragma unroll
    for (int o = 16; o; o >>= 1) sq += __shfl_xor_sync(0xffffffffu, sq, o);
    if ((t & 31) == 0) s2[t >> 5] = sq;
    __syncthreads();
    if (t == 0){
        float nrm   = sqrtf(s2[0] + s2[1]);
        float beta  = softplusf(c[768 + h]);
        float gate  = sigmoidf(c[772 + h]);
        float gamma = 1.f + softplusf(c[788 + h]);
        float a0 = c[776 + h*3 + 0], a1 = c[776 + h*3 + 1], a2 = c[776 + h*3 + 2];
        float m  = fmaxf(a0, fmaxf(a1, a2));
        float e0 = expf(a0 - m), e1 = expf(a1 - m), e2 = expf(a2 - m);
        float inv = 1.f/(e0 + e1 + e2);
        float* p = g_params + bh*8;
        p[0]=beta; p[1]=gate; p[2]=e0*inv; p[3]=e1*inv; p[4]=e2*inv; p[5]=gamma; p[6]=nrm;
    }
}

// ---------------- k1: beta * cosine scores -------------------------------
// Phase A: 128 threads load 128 rows (2048 float4) fully coalesced into padded SMEM.
// Phase B: one THREAD per row — conflict-free LDS (pitch 17), broadcast key loads,
//          zero shuffles.
#define K1T 128
#define K1_ROWSPB 128
#define TP 17                     // row pitch in float4
__global__ __launch_bounds__(K1T) void k1_scores(const float* __restrict__ mem){
    int b  = blockIdx.y;
    int n0 = blockIdx.x * K1_ROWSPB;
    __shared__ float4 tile[K1_ROWSPB * TP];
    __shared__ float skey[HH*WW];
    __shared__ float sb[HH], skn[HH];
    int t = threadIdx.x;
    skey[t]       = g_keys[b*HH*WW + t];
    skey[t + 128] = g_keys[b*HH*WW + t + 128];
    if (t < HH){ sb[t] = g_params[(b*HH + t)*8 + 0]; skn[t] = g_params[(b*HH + t)*8 + 6]; }

    // coalesced streaming load (MLP-heavy), scatter to padded SMEM
    const float4* gsrc = (const float4*)mem + ((size_t)b*NN + n0)*(WW/4);
    #pragma unroll
    for (int i = 0; i < 16; i++){
        int g = t + K1T*i;
        float4 v = __ldcs(gsrc + g);
        tile[(g >> 4)*TP + (g & 15)] = v;
    }
    __syncthreads();

    // one row per thread; keys via broadcast LDS; no shuffles
    const float4* mrow = tile + t*TP;
    const float4* kk   = (const float4*)skey;
    float d0 = 0.f, d1 = 0.f, d2 = 0.f, d3 = 0.f, sq = 0.f;
    #pragma unroll
    for (int j = 0; j < 16; j++){
        float4 m  = mrow[j];
        float4 c0 = kk[0*16 + j];
        float4 c1 = kk[1*16 + j];
        float4 c2 = kk[2*16 + j];
        float4 c3 = kk[3*16 + j];
        sq += m.x*m.x + m.y*m.y + m.z*m.z + m.w*m.w;
        d0 += m.x*c0.x + m.y*c0.y + m.z*c0.z + m.w*c0.w;
        d1 += m.x*c1.x + m.y*c1.y + m.z*c1.z + m.w*c1.w;
        d2 += m.x*c2.x + m.y*c2.y + m.z*c2.z + m.w*c2.w;
        d3 += m.x*c3.x + m.y*c3.y + m.z*c3.z + m.w*c3.w;
    }
    float mn = sqrtf(sq);
    size_t base = (size_t)b*HH*NN + n0 + t;
    g_scores[base + 0*(size_t)NN] = sb[0]*d0/(skn[0]*mn + 1e-8f);
    g_scores[base + 1*(size_t)NN] = sb[1]*d1/(skn[1]*mn + 1e-8f);
    g_scores[base + 2*(size_t)NN] = sb[2]*d2/(skn[2]*mn + 1e-8f);
    g_scores[base + 3*(size_t)NN] = sb[3]*d3/(skn[3]*mn + 1e-8f);
}

// ---------------- k2: softmax + interp + shift + sharpen ----------------
#define K2T 1024
#define VT  8
__device__ __forceinline__ float blk_reduce(float v, bool is_max, float* red, float* bc){
    int t = threadIdx.x, lane = t & 31, wid = t >> 5;
    #pragma unroll
    for (int o = 16; o; o >>= 1){
        float u = __shfl_xor_sync(0xffffffffu, v, o);
        v = is_max ? fmaxf(v, u) : (v + u);
    }
    __syncthreads();                 // protect red/bc from previous round
    if (lane == 0) red[wid] = v;
    __syncthreads();
    if (t == 0){
        float a = red[0];
        #pragma unroll
        for (int k = 1; k < K2T/32; k++) a = is_max ? fmaxf(a, red[k]) : (a + red[k]);
        *bc = a;
    }
    __syncthreads();
    return *bc;
}

__global__ __launch_bounds__(K2T) void k2_weights(const float* __restrict__ prev){
    int bh = blockIdx.x;
    __shared__ float sm[NN];
    __shared__ float red[K2T/32];
    __shared__ float bc;
    int t = threadIdx.x;

    const float* p = g_params + bh*8;
    float gate = p[1], s0 = p[2], s1 = p[3], s2 = p[4], gamma = p[5];

    const float* sc = g_scores + (size_t)bh*NN;
    const float* pr = prev     + (size_t)bh*NN;

    float4 v0 = ((const float4*)sc)[t*2];
    float4 v1 = ((const float4*)sc)[t*2 + 1];
    float4 p0 = ((const float4*)pr)[t*2];
    float4 p1 = ((const float4*)pr)[t*2 + 1];

    float v[VT] = {v0.x, v0.y, v0.z, v0.w, v1.x, v1.y, v1.z, v1.w};
    float pv[VT] = {p0.x, p0.y, p0.z, p0.w, p1.x, p1.y, p1.z, p1.w};

    float lmax = v[0];
    #pragma unroll
    for (int j = 1; j < VT; j++) lmax = fmaxf(lmax, v[j]);
    float M = blk_reduce(lmax, true, red, &bc);

    float lsum = 0.f;
    #pragma unroll
    for (int j = 0; j < VT; j++){ v[j] = __expf(v[j] - M); lsum += v[j]; }
    float S = blk_reduce(lsum, false, red, &bc);
    float invS = 1.f / S;

    #pragma unroll
    for (int j = 0; j < VT; j++)
        sm[t*VT + j] = gate * (v[j] * invS) + (1.f - gate) * pv[j];
    __syncthreads();

    float ls = 0.f;
    #pragma unroll
    for (int j = 0; j < VT; j++){
        int n  = t*VT + j;
        int nm = (n + NN - 1) & (NN - 1);
        int np = (n + 1) & (NN - 1);
        float x = s0*sm[nm] + s1*sm[n] + s2*sm[np];
        float pw = __powf(x, gamma);
        v[j] = pw;
        ls += pw;
    }
    float T = blk_reduce(ls, false, red, &bc);
    float invT = 1.f / (T + 1e-8f);

    float* wout = g_w + (size_t)bh*NN;
    float4 o0 = {v[0]*invT, v[1]*invT, v[2]*invT, v[3]*invT};
    float4 o1 = {v[4]*invT, v[5]*invT, v[6]*invT, v[7]*invT};
    ((float4*)wout)[t*2]     = o0;
    ((float4*)wout)[t*2 + 1] = o1;
}

// ---------------- k3: erase/add update, MLP=8 front-batched (R7 best) ----------
#define K3_ROWS 128
__global__ __launch_bounds__(256) void k3_out(const float* __restrict__ mem,
                                              float* __restrict__ out){
    int b  = blockIdx.y;
    int n0 = blockIdx.x * K3_ROWS;
    __shared__ float se[HH][WW], sv[HH][WW];
    __shared__ float sa[HH][K3_ROWS];
    int t = threadIdx.x;
    se[t >> 6][t & 63] = g_erase[b*HH*WW + t];
    sv[t >> 6][t & 63] = g_wvec [b*HH*WW + t];
    {   // coalesced preload of the 4x128 weight tile (2 per thread)
        int i0 = t, i1 = t + 256;
        sa[i0 >> 7][i0 & 127] = g_w[((size_t)b*HH + (i0 >> 7))*NN + n0 + (i0 & 127)];
        sa[i1 >> 7][i1 & 127] = g_w[((size_t)b*HH + (i1 >> 7))*NN + n0 + (i1 & 127)];
    }
    __syncthreads();

    int lane = t & 15, r = t >> 4;
    float4 e0 = ((const float4*)se[0])[lane];
    float4 e1 = ((const float4*)se[1])[lane];
    float4 e2 = ((const float4*)se[2])[lane];
    float4 e3 = ((const float4*)se[3])[lane];
    float4 w0 = ((const float4*)sv[0])[lane];
    float4 w1 = ((const float4*)sv[1])[lane];
    float4 w2 = ((const float4*)sv[2])[lane];
    float4 w3 = ((const float4*)sv[3])[lane];

    size_t base = ((size_t)b*NN + n0 + r)*16 + lane;

    float4 m[8];
    #pragma unroll
    for (int i = 0; i < 8; i++)
        m[i] = __ldcs((const float4*)mem + base + (size_t)16*16*i);

    #pragma unroll
    for (int i = 0; i < 8; i++){
        int rr = r + 16*i;
        float a0 = sa[0][rr], a1 = sa[1][rr], a2 = sa[2][rr], a3 = sa[3][rr];
        float4 o;
        o.x = m[i].x*(1.f-a0*e0.x)*(1.f-a1*e1.x)*(1.f-a2*e2.x)*(1.f-a3*e3.x)
            + a0*w0.x + a1*w1.x + a2*w2.x + a3*w3.x;
        o.y = m[i].y*(1.f-a0*e0.y)*(1.f-a1*e1.y)*(1.f-a2*e2.y)*(1.f-a3*e3.y)
            + a0*w0.y + a1*w1.y + a2*w2.y + a3*w3.y;
        o.z = m[i].z*(1.f-a0*e0.z)*(1.f-a1*e1.z)*(1.f-a2*e2.z)*(1.f-a3*e3.z)
            + a0*w0.z + a1*w1.z + a2*w2.z + a3*w3.z;
        o.w = m[i].w*(1.f-a0*e0.w)*(1.f-a1*e1.w)*(1.f-a2*e2.w)*(1.f-a3*e3.w)
            + a0*w0.w + a1*w1.w + a2*w2.w + a3*w3.w;
        __stcs((float4*)out + base + (size_t)16*16*i, o);
    }
}

// ---------------- launch ----------------
extern "C" void kernel_launch(void* const* d_in, const int* in_sizes, int n_in,
                              void* d_out, int out_size) {
    const float* mem  = (const float*)d_in[0];   // [B,N,W]
    const float* ctrl = (const float*)d_in[1];   // [B,792]
    const float* prev = (const float*)d_in[2];   // [B,H,N]
    float* out = (float*)d_out;                  // [B,N,W]

    k0_controls<<<BB*HH, 64>>>(ctrl);
    k1_scores  <<<dim3(NN/K1_ROWSPB, BB), K1T>>>(mem);
    k2_weights <<<BB*HH, K2T>>>(prev);
    k3_out     <<<dim3(NN/K3_ROWS, BB), 256>>>(mem, out);
    (void)in_sizes; (void)n_in; (void)out_size;
}

// round 10
// speedup vs baseline: 1.6412x; 1.2951x over previous
#include <cuda_runtime.h>
#include <math.h>

#define BB 64
#define NN 8192
#define WW 64
#define HH 4
#define CTRL 792   // H*(3W+6)
#define K1TILES 64 // NN / K1_ROWSPB

// ---------------- scratch (no allocation allowed) ----------------
__device__ float g_keys [BB*HH*WW];   // tanh(keys)
__device__ float g_erase[BB*HH*WW];   // sigmoid(erase)
__device__ float g_wvec [BB*HH*WW];   // tanh(write)
__device__ float g_params[BB*HH*8];   // beta,gate,s0,s1,s2,gamma,keynorm
__device__ float g_scores[(size_t)BB*HH*NN];  // beta * cosine
__device__ float g_w     [(size_t)BB*HH*NN];  // UNNORMALIZED sharpened weights
__device__ float g_pmax [BB*HH*K1TILES];      // per-tile score max
__device__ float g_psum [BB*HH*K1TILES];      // per-tile sum exp(s - pmax)
__device__ float g_tpart[BB*HH*4];            // per-tile sharpen partial sums

__device__ __forceinline__ float softplusf(float x){
    return x > 20.f ? x : log1pf(expf(x));
}
__device__ __forceinline__ float sigmoidf(float x){
    return 1.f/(1.f + expf(-x));
}

// ---------------- k0: control transforms (tiny) ----------------
__global__ void k0_controls(const float* __restrict__ ctrl){
    int bh = blockIdx.x;                 // b*4+h
    int b  = bh >> 2, h = bh & 3;
    int t  = threadIdx.x;                // 64 threads
    const float* c = ctrl + b*CTRL;

    float k = tanhf(c[h*WW + t]);
    g_keys [bh*WW + t] = k;
    g_erase[bh*WW + t] = sigmoidf(c[256 + h*WW + t]);
    g_wvec [bh*WW + t] = tanhf(c[512 + h*WW + t]);

    __shared__ float s2[2];
    float sq = k*k;
    #pragma unroll
    for (int o = 16; o; o >>= 1) sq += __shfl_xor_sync(0xffffffffu, sq, o);
    if ((t & 31) == 0) s2[t >> 5] = sq;
    __syncthreads();
    if (t == 0){
        float nrm   = sqrtf(s2[0] + s2[1]);
        float beta  = softplusf(c[768 + h]);
        float gate  = sigmoidf(c[772 + h]);
        float gamma = 1.f + softplusf(c[788 + h]);
        float a0 = c[776 + h*3 + 0], a1 = c[776 + h*3 + 1], a2 = c[776 + h*3 + 2];
        float m  = fmaxf(a0, fmaxf(a1, a2));
        float e0 = expf(a0 - m), e1 = expf(a1 - m), e2 = expf(a2 - m);
        float inv = 1.f/(e0 + e1 + e2);
        float* p = g_params + bh*8;
        p[0]=beta; p[1]=gate; p[2]=e0*inv; p[3]=e1*inv; p[4]=e2*inv; p[5]=gamma; p[6]=nrm;
    }
}

// ---------------- k1: scores + per-tile softmax partials ----------------
#define K1T 128
#define K1_ROWSPB 128
#define TP 17                     // row pitch in float4
__global__ __launch_bounds__(K1T) void k1_scores(const float* __restrict__ mem){
    int b  = blockIdx.y;
    int n0 = blockIdx.x * K1_ROWSPB;
    __shared__ float4 tile[K1_ROWSPB * TP];
    __shared__ float skey[HH*WW];
    __shared__ float sb[HH], skn[HH];
    __shared__ float rmax[4][HH], rsum[4][HH], bmax[HH];
    int t = threadIdx.x;
    skey[t]       = g_keys[b*HH*WW + t];
    skey[t + 128] = g_keys[b*HH*WW + t + 128];
    if (t < HH){ sb[t] = g_params[(b*HH + t)*8 + 0]; skn[t] = g_params[(b*HH + t)*8 + 6]; }

    const float4* gsrc = (const float4*)mem + ((size_t)b*NN + n0)*(WW/4);
    #pragma unroll
    for (int i = 0; i < 16; i++){
        int g = t + K1T*i;
        float4 v = __ldcs(gsrc + g);
        tile[(g >> 4)*TP + (g & 15)] = v;
    }
    __syncthreads();

    const float4* mrow = tile + t*TP;
    const float4* kk   = (const float4*)skey;
    float d0 = 0.f, d1 = 0.f, d2 = 0.f, d3 = 0.f, sq = 0.f;
    #pragma unroll
    for (int j = 0; j < 16; j++){
        float4 m  = mrow[j];
        float4 c0 = kk[0*16 + j];
        float4 c1 = kk[1*16 + j];
        float4 c2 = kk[2*16 + j];
        float4 c3 = kk[3*16 + j];
        sq += m.x*m.x + m.y*m.y + m.z*m.z + m.w*m.w;
        d0 += m.x*c0.x + m.y*c0.y + m.z*c0.z + m.w*c0.w;
        d1 += m.x*c1.x + m.y*c1.y + m.z*c1.z + m.w*c1.w;
        d2 += m.x*c2.x + m.y*c2.y + m.z*c2.z + m.w*c2.w;
        d3 += m.x*c3.x + m.y*c3.y + m.z*c3.z + m.w*c3.w;
    }
    float mn  = sqrtf(sq);
    float s[HH];
    s[0] = sb[0]*d0/(skn[0]*mn + 1e-8f);
    s[1] = sb[1]*d1/(skn[1]*mn + 1e-8f);
    s[2] = sb[2]*d2/(skn[2]*mn + 1e-8f);
    s[3] = sb[3]*d3/(skn[3]*mn + 1e-8f);
    size_t base = (size_t)b*HH*NN + n0 + t;
    #pragma unroll
    for (int h = 0; h < HH; h++) g_scores[base + (size_t)h*NN] = s[h];

    // block max per head (4 warps)
    int wid = t >> 5, lane = t & 31;
    #pragma unroll
    for (int h = 0; h < HH; h++){
        float v = s[h];
        #pragma unroll
        for (int o = 16; o; o >>= 1) v = fmaxf(v, __shfl_xor_sync(0xffffffffu, v, o));
        if (lane == 0) rmax[wid][h] = v;
    }
    __syncthreads();
    if (t < HH)
        bmax[t] = fmaxf(fmaxf(rmax[0][t], rmax[1][t]), fmaxf(rmax[2][t], rmax[3][t]));
    __syncthreads();
    // block sum of exp(s - bmax)
    #pragma unroll
    for (int h = 0; h < HH; h++){
        float v = __expf(s[h] - bmax[h]);
        #pragma unroll
        for (int o = 16; o; o >>= 1) v += __shfl_xor_sync(0xffffffffu, v, o);
        if (lane == 0) rsum[wid][h] = v;
    }
    __syncthreads();
    if (t < HH){
        int idx = (b*HH + t)*K1TILES + blockIdx.x;
        g_pmax[idx] = bmax[t];
        g_psum[idx] = rsum[0][t] + rsum[1][t] + rsum[2][t] + rsum[3][t];
    }
}

// ---------------- k2': tiled softmax-apply + interp + shift + sharpen ----------
// grid = BB*HH*4, 256 threads, 2048 elems/tile. Writes UNNORMALIZED w + partial T.
#define K2B 256
#define K2TILE 2048
__global__ __launch_bounds__(K2B) void k2_weights(const float* __restrict__ prev){
    int blk  = blockIdx.x;
    int bh   = blk >> 2;
    int tilei= blk & 3;
    int t0   = tilei * K2TILE;
    __shared__ float wi[K2TILE + 2];    // w_interp halo: [t0-1 .. t0+K2TILE]
    __shared__ float sMS[2];            // M, invS
    __shared__ float red[K2B/32];
    int t = threadIdx.x;

    // warp 0: combine the 64 per-tile partials into global (M, invS)
    if (t < 32){
        float pm0 = g_pmax[bh*K1TILES + t];
        float pm1 = g_pmax[bh*K1TILES + t + 32];
        float ps0 = g_psum[bh*K1TILES + t];
        float ps1 = g_psum[bh*K1TILES + t + 32];
        float m = fmaxf(pm0, pm1);
        #pragma unroll
        for (int o = 16; o; o >>= 1) m = fmaxf(m, __shfl_xor_sync(0xffffffffu, m, o));
        float ss = ps0*__expf(pm0 - m) + ps1*__expf(pm1 - m);
        #pragma unroll
        for (int o = 16; o; o >>= 1) ss += __shfl_xor_sync(0xffffffffu, ss, o);
        if (t == 0){ sMS[0] = m; sMS[1] = 1.f/ss; }
    }

    const float* p = g_params + bh*8;
    float gate = p[1], s0 = p[2], s1 = p[3], s2 = p[4], gamma = p[5];
    const float* sc = g_scores + (size_t)bh*NN;
    const float* pr = prev     + (size_t)bh*NN;
    __syncthreads();
    float M = sMS[0], invS = sMS[1];

    // main tile: 8 elems/thread via float4
    float4 v0 = ((const float4*)(sc + t0))[t*2];
    float4 v1 = ((const float4*)(sc + t0))[t*2 + 1];
    float4 p0 = ((const float4*)(pr + t0))[t*2];
    float4 p1 = ((const float4*)(pr + t0))[t*2 + 1];
    float v[8]  = {v0.x, v0.y, v0.z, v0.w, v1.x, v1.y, v1.z, v1.w};
    float pv[8] = {p0.x, p0.y, p0.z, p0.w, p1.x, p1.y, p1.z, p1.w};
    #pragma unroll
    for (int j = 0; j < 8; j++)
        wi[1 + t*8 + j] = gate * (__expf(v[j] - M) * invS) + (1.f - gate) * pv[j];
    // halo
    if (t == 0){
        int n = (t0 + NN - 1) & (NN - 1);
        wi[0] = gate * (__expf(sc[n] - M) * invS) + (1.f - gate) * pr[n];
    }
    if (t == 1){
        int n = (t0 + K2TILE) & (NN - 1);
        wi[K2TILE + 1] = gate * (__expf(sc[n] - M) * invS) + (1.f - gate) * pr[n];
    }
    __syncthreads();

    float pw[8];
    float ls = 0.f;
    #pragma unroll
    for (int j = 0; j < 8; j++){
        int l = t*8 + j;
        float x = s0*wi[l] + s1*wi[l + 1] + s2*wi[l + 2];
        pw[j] = __powf(x, gamma);
        ls += pw[j];
    }
    // block-reduce ls, emit partial T
    int lane = t & 31, wid = t >> 5;
    #pragma unroll
    for (int o = 16; o; o >>= 1) ls += __shfl_xor_sync(0xffffffffu, ls, o);
    if (lane == 0) red[wid] = ls;
    __syncthreads();
    if (t == 0){
        float a = red[0];
        #pragma unroll
        for (int k = 1; k < K2B/32; k++) a += red[k];
        g_tpart[bh*4 + tilei] = a;
    }

    float* wout = g_w + (size_t)bh*NN + t0;
    float4 o0 = {pw[0], pw[1], pw[2], pw[3]};
    float4 o1 = {pw[4], pw[5], pw[6], pw[7]};
    ((float4*)wout)[t*2]     = o0;
    ((float4*)wout)[t*2 + 1] = o1;
}

// ---------------- k3: erase/add update; folds in final normalization ----------
#define K3_ROWS 128
__global__ __launch_bounds__(256) void k3_out(const float* __restrict__ mem,
                                              float* __restrict__ out){
    int b  = blockIdx.y;
    int n0 = blockIdx.x * K3_ROWS;
    __shared__ float se[HH][WW], sv[HH][WW];
    __shared__ float sa[HH][K3_ROWS];
    __shared__ float sInvT[HH];
    int t = threadIdx.x;
    se[t >> 6][t & 63] = g_erase[b*HH*WW + t];
    sv[t >> 6][t & 63] = g_wvec [b*HH*WW + t];
    if (t < HH){
        int base = (b*HH + t)*4;
        float T = g_tpart[base] + g_tpart[base+1] + g_tpart[base+2] + g_tpart[base+3];
        sInvT[t] = 1.f/(T + 1e-8f);
    }
    {   // coalesced preload of the 4x128 weight tile (2 per thread)
        int i0 = t, i1 = t + 256;
        sa[i0 >> 7][i0 & 127] = g_w[((size_t)b*HH + (i0 >> 7))*NN + n0 + (i0 & 127)];
        sa[i1 >> 7][i1 & 127] = g_w[((size_t)b*HH + (i1 >> 7))*NN + n0 + (i1 & 127)];
    }
    __syncthreads();

    int lane = t & 15, r = t >> 4;
    float4 e0 = ((const float4*)se[0])[lane];
    float4 e1 = ((const float4*)se[1])[lane];
    float4 e2 = ((const float4*)se[2])[lane];
    float4 e3 = ((const float4*)se[3])[lane];
    float4 w0 = ((const float4*)sv[0])[lane];
    float4 w1 = ((const float4*)sv[1])[lane];
    float4 w2 = ((const float4*)sv[2])[lane];
    float4 w3 = ((const float4*)sv[3])[lane];
    float it0 = sInvT[0], it1 = sInvT[1], it2 = sInvT[2], it3 = sInvT[3];

    size_t base = ((size_t)b*NN + n0 + r)*16 + lane;

    float4 m[8];
    #pragma unroll
    for (int i = 0; i < 8; i++)
        m[i] = __ldcs((const float4*)mem + base + (size_t)16*16*i);

    #pragma unroll
    for (int i = 0; i < 8; i++){
        int rr = r + 16*i;
        float a0 = sa[0][rr]*it0, a1 = sa[1][rr]*it1,
              a2 = sa[2][rr]*it2, a3 = sa[3][rr]*it3;
        float4 o;
        o.x = m[i].x*(1.f-a0*e0.x)*(1.f-a1*e1.x)*(1.f-a2*e2.x)*(1.f-a3*e3.x)
            + a0*w0.x + a1*w1.x + a2*w2.x + a3*w3.x;
        o.y = m[i].y*(1.f-a0*e0.y)*(1.f-a1*e1.y)*(1.f-a2*e2.y)*(1.f-a3*e3.y)
            + a0*w0.y + a1*w1.y + a2*w2.y + a3*w3.y;
        o.z = m[i].z*(1.f-a0*e0.z)*(1.f-a1*e1.z)*(1.f-a2*e2.z)*(1.f-a3*e3.z)
            + a0*w0.z + a1*w1.z + a2*w2.z + a3*w3.z;
        o.w = m[i].w*(1.f-a0*e0.w)*(1.f-a1*e1.w)*(1.f-a2*e2.w)*(1.f-a3*e3.w)
            + a0*w0.w + a1*w1.w + a2*w2.w + a3*w3.w;
        __stcs((float4*)out + base + (size_t)16*16*i, o);
    }
}

// ---------------- launch ----------------
extern "C" void kernel_launch(void* const* d_in, const int* in_sizes, int n_in,
                              void* d_out, int out_size) {
    const float* mem  = (const float*)d_in[0];   // [B,N,W]
    const float* ctrl = (const float*)d_in[1];   // [B,792]
    const float* prev = (const float*)d_in[2];   // [B,H,N]
    float* out = (float*)d_out;                  // [B,N,W]

    k0_controls<<<BB*HH, 64>>>(ctrl);
    k1_scores  <<<dim3(NN/K1_ROWSPB, BB), K1T>>>(mem);
    k2_weights <<<BB*HH*4, K2B>>>(prev);
    k3_out     <<<dim3(NN/K3_ROWS, BB), 256>>>(mem, out);
    (void)in_sizes; (void)n_in; (void)out_size;
}